// round 5
// baseline (speedup 1.0000x reference)
#include <cuda_runtime.h>
#include <cuda_bf16.h>
#include <stdint.h>

#define T_TOK 1024
#define D_DIM 1024
#define F_DIM 2048
#define E_EXP 32
#define TOPK  4
#define NPAIR (T_TOK * TOPK)

// ---------------- static scratch ----------------
__device__ int      g_cnt[E_EXP];
__device__ int      g_pairs[E_EXP * T_TOK];
__device__ float    g_w[NPAIR];
__device__ uint32_t g_hp[(size_t)NPAIR * F_DIM];   // routed hidden packed bf16 hi|lo<<16
__device__ uint32_t g_hsp[(size_t)T_TOK * F_DIM];  // shared hidden packed
__device__ float    g_y[(size_t)NPAIR * D_DIM];    // routed per-pair down output

// ---------------- helpers ----------------
__device__ __forceinline__ uint32_t smem_u32(const void* p) {
    uint32_t a;
    asm("{ .reg .u64 t; cvta.to.shared.u64 t, %1; cvt.u32.u64 %0, t; }" : "=r"(a) : "l"(p));
    return a;
}
__device__ __forceinline__ void ldm4(uint32_t* r, uint32_t addr) {
    asm volatile("ldmatrix.sync.aligned.m8n8.x4.shared.b16 {%0,%1,%2,%3}, [%4];"
                 : "=r"(r[0]), "=r"(r[1]), "=r"(r[2]), "=r"(r[3]) : "r"(addr));
}
__device__ __forceinline__ void mma16816(float* d, const uint32_t* a, const uint32_t* b) {
    asm volatile("mma.sync.aligned.m16n8k16.row.col.f32.bf16.bf16.f32 "
                 "{%0,%1,%2,%3}, {%4,%5,%6,%7}, {%8,%9}, {%0,%1,%2,%3};"
                 : "+f"(d[0]), "+f"(d[1]), "+f"(d[2]), "+f"(d[3])
                 : "r"(a[0]), "r"(a[1]), "r"(a[2]), "r"(a[3]), "r"(b[0]), "r"(b[1]));
}
__device__ __forceinline__ void cvt_split(float x0, float x1, uint32_t& hi, uint32_t& lo) {
    asm("cvt.rn.bf16x2.f32 %0, %1, %2;" : "=r"(hi) : "f"(x1), "f"(x0));
    float f0 = __uint_as_float(hi << 16);
    float f1 = __uint_as_float(hi & 0xffff0000u);
    float r0 = x0 - f0, r1 = x1 - f1;
    asm("cvt.rn.bf16x2.f32 %0, %1, %2;" : "=r"(lo) : "f"(r1), "f"(r0));
}
__device__ __forceinline__ void split_store4(char* hi, char* lo, float4 v) {
    uint32_t h0, l0, h1, l1;
    cvt_split(v.x, v.y, h0, l0);
    cvt_split(v.z, v.w, h1, l1);
    *(uint2*)hi = make_uint2(h0, h1);
    *(uint2*)lo = make_uint2(l0, l1);
}
__device__ __forceinline__ uint32_t pack_split1(float h) {
    __nv_bfloat16 hb = __float2bfloat16_rn(h);
    float r = h - __bfloat162float(hb);
    __nv_bfloat16 lb = __float2bfloat16_rn(r);
    return (uint32_t)__bfloat16_as_ushort(hb) | ((uint32_t)__bfloat16_as_ushort(lb) << 16);
}

// ---------------- tiny kernels ----------------
__global__ void zero_kernel() {
    if (threadIdx.x < E_EXP) g_cnt[threadIdx.x] = 0;
}

__global__ void router_kernel(const float* __restrict__ x,
                              const float* __restrict__ gw,
                              const float* __restrict__ bias) {
    __shared__ float xs[D_DIM];
    __shared__ float logits[E_EXP];
    int t = blockIdx.x;
    const float4* xr = (const float4*)(x + (size_t)t * D_DIM);
    for (int i = threadIdx.x; i < D_DIM / 4; i += blockDim.x)
        ((float4*)xs)[i] = xr[i];
    __syncthreads();

    int e = threadIdx.x >> 2;
    int g = threadIdx.x & 3;
    const float4* wrow = (const float4*)(gw + (size_t)e * D_DIM);
    float s = 0.f;
    for (int d4 = g; d4 < D_DIM / 4; d4 += 4) {
        float4 a = ((const float4*)xs)[d4];
        float4 b = wrow[d4];
        s += a.x * b.x + a.y * b.y + a.z * b.z + a.w * b.w;
    }
    s += __shfl_down_sync(0xffffffffu, s, 2, 4);
    s += __shfl_down_sync(0xffffffffu, s, 1, 4);
    if (g == 0) logits[e] = s + bias[e];
    __syncthreads();

    if (threadIdx.x == 0) {
        float v[TOPK]; int idx[TOPK];
        unsigned used = 0;
        for (int k = 0; k < TOPK; k++) {
            float best = -3.4e38f; int bi = 0;
            for (int j = 0; j < E_EXP; j++) {
                if (used & (1u << j)) continue;
                if (logits[j] > best) { best = logits[j]; bi = j; }
            }
            used |= 1u << bi; v[k] = best; idx[k] = bi;
        }
        float ex[TOPK], sum = 0.f;
        for (int k = 0; k < TOPK; k++) { ex[k] = __expf(v[k] - v[0]); sum += ex[k]; }
        float inv = 1.f / sum;
        for (int k = 0; k < TOPK; k++) {
            int ek = idx[k];
            int slot = atomicAdd(&g_cnt[ek], 1);
            g_pairs[ek * T_TOK + slot] = t * TOPK + k;
            g_w[t * TOPK + k] = ex[k] * inv;
        }
    }
}

__global__ void stats_kernel(float* __restrict__ tail) {
    int e = threadIdx.x;
    float c = (float)g_cnt[e];
    float mean = (float)(T_TOK * TOPK) / E_EXP;
    float d = c - mean;
    float v = d * d;
    for (int o = 16; o > 0; o >>= 1) v += __shfl_down_sync(0xffffffffu, v, o);
    if (tail) {
        tail[e] = c;
        if (e == 0) tail[E_EXP] = sqrtf(v / E_EXP) / (mean + 1e-6f);
    }
}

// ================= gate+up warp-MMA =================
// CTA 128M x 128N(F), 512 thr, 16 warps: 8 gate + 8 up, each 32x64. BK=32.
#define PIT   80               // 32 bf16 = 64B + 16 pad
#define SA_HI 0
#define SA_LO 10240
#define SG_HI 20480
#define SG_LO 30720
#define SU_HI 40960
#define SU_LO 51200
#define STAGE_SZ 61440
#define GU_SMEM 137216
#define DN_SMEM 135168

__global__ void __launch_bounds__(512, 1)
gu_mma(const float* __restrict__ x,
       const float* __restrict__ Wg, const float* __restrict__ Wu,
       const float* __restrict__ wsg, const float* __restrict__ wsu) {
    extern __shared__ char smem[];
    int tid = threadIdx.x;
    int z = blockIdx.z;
    bool SH = (z == E_EXP);
    int ne = SH ? T_TOK : g_cnt[z];
    int m0 = blockIdx.y * 128;
    if (m0 >= ne) return;
    int n0 = blockIdx.x * 128;
    const float* wgp = SH ? wsg : (Wg + (size_t)z * F_DIM * D_DIM);
    const float* wup = SH ? wsu : (Wu + (size_t)z * F_DIM * D_DIM);

    int* s_pair = (int*)smem;
    int* s_src  = (int*)(smem + 512);
    if (tid < 128) {
        int m = m0 + tid;
        int pair = SH ? m : ((m < ne) ? g_pairs[z * T_TOK + m] : g_pairs[z * T_TOK]);
        s_pair[tid] = pair;
        s_src[tid]  = SH ? m : (pair >> 2);
    }
    __syncthreads();

    const int lr = tid >> 2, lc = tid & 3;
    const float* aP = x   + (size_t)s_src[lr] * D_DIM + lc * 4;
    const float* gP = wgp + (size_t)(n0 + lr) * D_DIM + lc * 4;
    const float* uP = wup + (size_t)(n0 + lr) * D_DIM + lc * 4;
    const unsigned so0 = lr * PIT + lc * 8, so1 = lr * PIT + (lc + 4) * 8;

    const int wid = tid >> 5, lane = tid & 31;
    const bool isUp = wid >= 8;
    const int q = wid & 7;
    const int wm = q >> 1, wn = q & 1;          // rows wm*32, cols wn*64
    const uint32_t a_row = wm * 32 + (lane & 15);
    const uint32_t a_cb  = (lane >> 4) * 16;
    const uint32_t b_row = wn * 64 + ((lane >> 3) >> 1) * 8 + (lane & 7);
    const uint32_t b_cb  = ((lane >> 3) & 1) * 16;

    float acc[2][8][4] = {};
    float4 pa0, pa1, pg0, pg1, pu0, pu1;
    pa0 = *(const float4*)aP;        pa1 = *(const float4*)(aP + 16);
    pg0 = *(const float4*)gP;        pg1 = *(const float4*)(gP + 16);
    pu0 = *(const float4*)uP;        pu1 = *(const float4*)(uP + 16);

#define GU_ST(B) do { char* b_ = (B); \
    split_store4(b_ + SA_HI + so0, b_ + SA_LO + so0, pa0); \
    split_store4(b_ + SA_HI + so1, b_ + SA_LO + so1, pa1); \
    split_store4(b_ + SG_HI + so0, b_ + SG_LO + so0, pg0); \
    split_store4(b_ + SG_HI + so1, b_ + SG_LO + so1, pg1); \
    split_store4(b_ + SU_HI + so0, b_ + SU_LO + so0, pu0); \
    split_store4(b_ + SU_HI + so1, b_ + SU_LO + so1, pu1); } while (0)

    GU_ST(smem + 1024);
    __syncthreads();

    for (int ch = 0; ch < 32; ++ch) {
        if (ch < 31) {
            int k0 = (ch + 1) * 32;
            pa0 = *(const float4*)(aP + k0); pa1 = *(const float4*)(aP + k0 + 16);
            pg0 = *(const float4*)(gP + k0); pg1 = *(const float4*)(gP + k0 + 16);
            pu0 = *(const float4*)(uP + k0); pu1 = *(const float4*)(uP + k0 + 16);
        }
        uint32_t ab = smem_u32(smem + 1024 + (ch & 1) * STAGE_SZ);
        uint32_t bb = ab + (isUp ? SU_HI : SG_HI);
#pragma unroll
        for (int s = 0; s < 2; ++s) {
            uint32_t koff = s * 32;
            uint32_t ah[2][4], al[2][4];
#pragma unroll
            for (int mt = 0; mt < 2; ++mt) {
                uint32_t ad = ab + SA_HI + (a_row + mt * 16) * PIT + koff + a_cb;
                ldm4(ah[mt], ad);
                ldm4(al[mt], ad + (SA_LO - SA_HI));
            }
#pragma unroll
            for (int h = 0; h < 2; ++h) {
                uint32_t bh[8], bl[8];
#pragma unroll
                for (int p = 0; p < 2; ++p) {
                    uint32_t bd = bb + (b_row + (h * 2 + p) * 16) * PIT + koff + b_cb;
                    ldm4(&bh[p * 4], bd);
                    ldm4(&bl[p * 4], bd + 10240);
                }
#pragma unroll
                for (int mt = 0; mt < 2; ++mt)
#pragma unroll
                    for (int nt = 0; nt < 4; ++nt) {
                        float* d = acc[mt][h * 4 + nt];
                        mma16816(d, ah[mt], &bh[nt * 2]);
                        mma16816(d, ah[mt], &bl[nt * 2]);
                        mma16816(d, al[mt], &bh[nt * 2]);
                    }
            }
        }
        if (ch < 31) {
            GU_ST(smem + 1024 + ((ch + 1) & 1) * STAGE_SZ);
            __syncthreads();
        }
    }
    __syncthreads();

    // epilogue: stage gate + up fp32 (128x128 each), silu, pack, store
    float* stg_g = (float*)(smem + 1024);
    float* stg_u = stg_g + 128 * 132;
    float* my = isUp ? stg_u : stg_g;
#pragma unroll
    for (int mt = 0; mt < 2; ++mt)
#pragma unroll
        for (int nt = 0; nt < 8; ++nt) {
            int r = wm * 32 + mt * 16 + (lane >> 2);
            int c = wn * 64 + nt * 8 + (lane & 3) * 2;
            *(float2*)&my[r * 132 + c]       = make_float2(acc[mt][nt][0], acc[mt][nt][1]);
            *(float2*)&my[(r + 8) * 132 + c] = make_float2(acc[mt][nt][2], acc[mt][nt][3]);
        }
    __syncthreads();

    uint32_t* dst = SH ? g_hsp : g_hp;
    {
        int r = tid >> 2, c0 = (tid & 3) * 32;
        uint32_t* drow = dst + (size_t)s_pair[r] * F_DIM + n0 + c0;
#pragma unroll
        for (int jj = 0; jj < 32; jj += 4) {
            uint4 o;
            uint32_t* po = &o.x;
#pragma unroll
            for (int k2 = 0; k2 < 4; ++k2) {
                float gg = stg_g[r * 132 + c0 + jj + k2];
                float uu = stg_u[r * 132 + c0 + jj + k2];
                float h = gg / (1.f + __expf(-gg)) * uu;
                po[k2] = pack_split1(h);
            }
            *(uint4*)(drow + jj) = o;
        }
    }
}

// ================= down warp-MMA =================
// CTA 128M x 256N(D), 512 thr, 16 warps 32x64 (4x4). BK=32 over F.
#define DA_HI 0
#define DA_LO 10240
#define DB_HI 20480
#define DB_LO 40960
#define DSTAGE 61440

template <bool SH>
__global__ void __launch_bounds__(512, 1)
dn_mma(const float* __restrict__ Wd, float* __restrict__ out) {
    extern __shared__ char smem[];
    int tid = threadIdx.x;
    int z = SH ? 0 : blockIdx.z;
    int ne = SH ? T_TOK : g_cnt[z];
    int m0 = blockIdx.y * 128;
    if (m0 >= ne) return;
    int n0 = blockIdx.x * 256;
    const float* wdp = SH ? Wd : (Wd + (size_t)z * D_DIM * F_DIM);
    const uint32_t* hsrc = SH ? g_hsp : g_hp;

    int* s_pair = (int*)smem;
    if (tid < 128) {
        int m = m0 + tid;
        s_pair[tid] = SH ? m : ((m < ne) ? g_pairs[z * T_TOK + m] : g_pairs[z * T_TOK]);
    }
    __syncthreads();

    // load assignment: 1024 A-f4 (threads k=0,1), 2048 B-f4 (k=2..5)
    const uint4*  pa[2]; unsigned soA[2];
    const float4* pb[4]; unsigned soB[4];
#pragma unroll
    for (int k2 = 0; k2 < 2; ++k2) {
        int idx = tid + 512 * k2;
        int row = idx >> 3, c = idx & 7;
        pa[k2]  = (const uint4*)(hsrc + (size_t)s_pair[row] * F_DIM + c * 4);
        soA[k2] = row * PIT + c * 8;
    }
#pragma unroll
    for (int k2 = 0; k2 < 4; ++k2) {
        int idx = tid + 512 * k2;   // +1024 offset folded: idx range 0..2047 via k2 base
        int row = idx >> 3, c = idx & 7;
        pb[k2]  = (const float4*)(wdp + (size_t)(n0 + row) * F_DIM + c * 4);
        soB[k2] = row * PIT + c * 8;
    }

    const int wid = tid >> 5, lane = tid & 31;
    const int wm = wid >> 2, wn = wid & 3;      // rows wm*32, cols wn*64
    const uint32_t a_row = wm * 32 + (lane & 15);
    const uint32_t a_cb  = (lane >> 4) * 16;
    const uint32_t b_row = wn * 64 + ((lane >> 3) >> 1) * 8 + (lane & 7);
    const uint32_t b_cb  = ((lane >> 3) & 1) * 16;

    float acc[2][8][4] = {};
    uint4  ra[2];
    float4 rb[4];
#pragma unroll
    for (int k2 = 0; k2 < 2; ++k2) ra[k2] = pa[k2][0];
#pragma unroll
    for (int k2 = 0; k2 < 4; ++k2) rb[k2] = pb[k2][0];

#define DN_ST(B) do { char* b_ = (B); \
    _Pragma("unroll") \
    for (int k2 = 0; k2 < 2; ++k2) { \
        uint32_t h0 = __byte_perm(ra[k2].x, ra[k2].y, 0x5410); \
        uint32_t h1 = __byte_perm(ra[k2].z, ra[k2].w, 0x5410); \
        uint32_t l0 = __byte_perm(ra[k2].x, ra[k2].y, 0x7632); \
        uint32_t l1 = __byte_perm(ra[k2].z, ra[k2].w, 0x7632); \
        *(uint2*)(b_ + DA_HI + soA[k2]) = make_uint2(h0, h1); \
        *(uint2*)(b_ + DA_LO + soA[k2]) = make_uint2(l0, l1); } \
    _Pragma("unroll") \
    for (int k2 = 0; k2 < 4; ++k2) \
        split_store4(b_ + DB_HI + soB[k2], b_ + DB_LO + soB[k2], rb[k2]); } while (0)

    DN_ST(smem + 1024);
    __syncthreads();

    for (int ch = 0; ch < 64; ++ch) {
        if (ch < 63) {
            int o4 = (ch + 1) * 8;  // 32 elements = 8 x f4
#pragma unroll
            for (int k2 = 0; k2 < 2; ++k2) ra[k2] = pa[k2][o4];
#pragma unroll
            for (int k2 = 0; k2 < 4; ++k2) rb[k2] = pb[k2][o4];
        }
        uint32_t ab = smem_u32(smem + 1024 + (ch & 1) * DSTAGE);
        uint32_t bb = ab + DB_HI;
#pragma unroll
        for (int s = 0; s < 2; ++s) {
            uint32_t koff = s * 32;
            uint32_t ah[2][4], al[2][4];
#pragma unroll
            for (int mt = 0; mt < 2; ++mt) {
                uint32_t ad = ab + DA_HI + (a_row + mt * 16) * PIT + koff + a_cb;
                ldm4(ah[mt], ad);
                ldm4(al[mt], ad + (DA_LO - DA_HI));
            }
#pragma unroll
            for (int h = 0; h < 2; ++h) {
                uint32_t bh[8], bl[8];
#pragma unroll
                for (int p = 0; p < 2; ++p) {
                    uint32_t bd = bb + (b_row + (h * 2 + p) * 16) * PIT + koff + b_cb;
                    ldm4(&bh[p * 4], bd);
                    ldm4(&bl[p * 4], bd + (DB_LO - DB_HI));
                }
#pragma unroll
                for (int mt = 0; mt < 2; ++mt)
#pragma unroll
                    for (int nt = 0; nt < 4; ++nt) {
                        float* d = acc[mt][h * 4 + nt];
                        mma16816(d, ah[mt], &bh[nt * 2]);
                        mma16816(d, ah[mt], &bl[nt * 2]);
                        mma16816(d, al[mt], &bh[nt * 2]);
                    }
            }
        }
        if (ch < 63) {
            DN_ST(smem + 1024 + ((ch + 1) & 1) * DSTAGE);
            __syncthreads();
        }
    }
    __syncthreads();

    float* stg = (float*)(smem + 1024);
#pragma unroll
    for (int mt = 0; mt < 2; ++mt)
#pragma unroll
        for (int nt = 0; nt < 8; ++nt) {
            int r = wm * 32 + mt * 16 + (lane >> 2);
            int c = wn * 64 + nt * 8 + (lane & 3) * 2;
            *(float2*)&stg[r * 260 + c]       = make_float2(acc[mt][nt][0], acc[mt][nt][1]);
            *(float2*)&stg[(r + 8) * 260 + c] = make_float2(acc[mt][nt][2], acc[mt][nt][3]);
        }
    __syncthreads();

    {
        int r = tid >> 2, c0 = (tid & 3) * 64;
        float* drow;
        if (SH) drow = out + (size_t)(m0 + r) * D_DIM + n0 + c0;
        else    drow = g_y + (size_t)s_pair[r] * D_DIM + n0 + c0;
#pragma unroll
        for (int jj = 0; jj < 64; jj += 4) {
            *(float4*)(drow + jj) = make_float4(stg[r * 260 + c0 + jj],     stg[r * 260 + c0 + jj + 1],
                                                stg[r * 260 + c0 + jj + 2], stg[r * 260 + c0 + jj + 3]);
        }
    }
}

// ================= combine: out += sum_k w_k * y_pair =================
__global__ void combine_kernel(float* __restrict__ out) {
    int t = blockIdx.x;
    int c = threadIdx.x * 4;
    float4 o = *(float4*)(out + (size_t)t * D_DIM + c);
#pragma unroll
    for (int k = 0; k < TOPK; ++k) {
        int pair = t * TOPK + k;
        float w = g_w[pair];
        float4 y = *(const float4*)(g_y + (size_t)pair * D_DIM + c);
        o.x += w * y.x; o.y += w * y.y; o.z += w * y.z; o.w += w * y.w;
    }
    *(float4*)(out + (size_t)t * D_DIM + c) = o;
}

// ---------------- launch ----------------
extern "C" void kernel_launch(void* const* d_in, const int* in_sizes, int n_in,
                              void* d_out, int out_size) {
    const float* x    = (const float*)d_in[0];
    const float* gw   = (const float*)d_in[1];
    const float* bias = (const float*)d_in[2];
    const float* wg   = (const float*)d_in[3];
    const float* wu   = (const float*)d_in[4];
    const float* wd   = (const float*)d_in[5];
    const float* wsg  = (const float*)d_in[6];
    const float* wsu  = (const float*)d_in[7];
    const float* wsd  = (const float*)d_in[8];
    float* out = (float*)d_out;

    static int attr_done = 0;
    if (!attr_done) {
        cudaFuncSetAttribute(gu_mma, cudaFuncAttributeMaxDynamicSharedMemorySize, GU_SMEM);
        cudaFuncSetAttribute(dn_mma<true>,  cudaFuncAttributeMaxDynamicSharedMemorySize, DN_SMEM);
        cudaFuncSetAttribute(dn_mma<false>, cudaFuncAttributeMaxDynamicSharedMemorySize, DN_SMEM);
        attr_done = 1;
    }

    zero_kernel<<<1, 32>>>();
    router_kernel<<<T_TOK, 128>>>(x, gw, bias);

    float* tail = (out_size >= T_TOK * D_DIM + E_EXP + 1) ? (out + T_TOK * D_DIM) : nullptr;
    stats_kernel<<<1, 32>>>(tail);

    // gate+up: routed z=0..31, shared z=32
    gu_mma<<<dim3(F_DIM / 128, T_TOK / 128, E_EXP + 1), 512, GU_SMEM>>>(x, wg, wu, wsg, wsu);

    // shared down: writes all of out
    dn_mma<true><<<dim3(D_DIM / 256, T_TOK / 128), 512, DN_SMEM>>>(wsd, out);

    // routed down: per-pair rows into g_y
    dn_mma<false><<<dim3(D_DIM / 256, T_TOK / 128, E_EXP), 512, DN_SMEM>>>(wd, out);

    // weighted combine
    combine_kernel<<<T_TOK, 256>>>(out);
}